// round 1
// baseline (speedup 1.0000x reference)
#include <cuda_runtime.h>
#include <cstdint>

#define B_    32
#define T_    128
#define NIN_  64
#define H_    512
#define DMAX_ 50
#define K_    4
#define HB_   128           // h per block
#define NHB_  (H_/HB_)      // 4 h-tiles

#define I_ELEMS   (T_ * HB_)      // 16384 floats
#define PITCH     65              // bank-conflict-free pitch for [h][i] tap arrays
#define TAP_ELEMS (HB_ * PITCH)   // 8320

// deterministic partial sums: [b][hb][k]
__device__ float g_partials[B_ * NHB_ * K_];

__global__ __launch_bounds__(HB_, 1)
void snn_main_kernel(const float* __restrict__ spikes,      // [B,T,NIN]
                     const float* __restrict__ w_ih,        // [H,NIN]
                     const float* __restrict__ delay_raw,   // [H,NIN]
                     const float* __restrict__ w_read,      // [H]
                     const float* __restrict__ slot_mask)   // [K,T]
{
    extern __shared__ char smem_raw[];
    float* I_sh    = (float*)smem_raw;                 // [T][HB]  65536 B
    float* w0_sh   = I_sh + I_ELEMS;                   // [HB][65] 33280 B
    float* w1_sh   = w0_sh + TAP_ELEMS;                // 33280 B
    int*   s_sh    = (int*)(w1_sh + TAP_ELEMS);        // 33280 B
    float* mask_sh = (float*)(s_sh + TAP_ELEMS);       // 2048 B
    unsigned long long* xlo = (unsigned long long*)(mask_sh + K_*T_); // 512 B
    unsigned long long* xhi = xlo + NIN_;                             // 512 B
    float* red     = (float*)(xhi + NIN_);             // 16 floats

    const int tid = threadIdx.x;
    const int hb  = blockIdx.x;
    const int b   = blockIdx.y;

    // ---- Phase 1a: zero I tile (bank = tid mod 32 -> conflict-free) ----
    #pragma unroll
    for (int t = 0; t < T_; t++) I_sh[t*HB_ + tid] = 0.f;

    // slot mask -> smem
    #pragma unroll
    for (int j = tid; j < K_*T_; j += HB_) mask_sh[j] = slot_mask[j];

    // ---- Phase 1b: bitpack spikes of batch b: column i, 128 time bits ----
    {
        int i    = tid >> 1;
        int half = tid & 1;                  // t in [0,64) or [64,128)
        const float* xp = spikes + (size_t)b * T_ * NIN_ + (size_t)(half * 64) * NIN_ + i;
        unsigned long long bits = 0ull;
        #pragma unroll 8
        for (int tb = 0; tb < 64; tb++) {
            float v = xp[(size_t)tb * NIN_];
            bits |= (unsigned long long)(v != 0.f) << tb;
        }
        if (half) xhi[i] = bits; else xlo[i] = bits;
    }

    // ---- Phase 1c: tap params (coalesced global reads) ----
    {
        const int base = hb * HB_ * NIN_;
        #pragma unroll
        for (int idx = tid; idx < HB_ * NIN_; idx += HB_) {
            int hh = idx >> 6;
            int ii = idx & 63;
            float raw  = delay_raw[base + idx];
            float d    = (float)DMAX_ / (1.f + expf(-raw));  // sigmoid * DMAX
            float d0   = floorf(d);
            float frac = d - d0;
            int   i0   = (int)d0;
            float w    = w_ih[base + idx];
            w0_sh[hh*PITCH + ii] = w * (1.f - frac);
            w1_sh[hh*PITCH + ii] = w * frac;
            s_sh [hh*PITCH + ii] = i0 + 1;                   // shift for tap0 (read-before-insert => +1)
        }
    }
    __syncthreads();

    // ---- Phase 2: sparse scatter of delayed weighted spikes into I_sh ----
    {
        const int rowbase = tid * PITCH;
        #pragma unroll 1
        for (int i = 0; i < NIN_; i++) {
            unsigned long long lo = xlo[i];   // broadcast LDS
            unsigned long long hi = xhi[i];
            if (!(lo | hi)) continue;
            int   s0 = s_sh [rowbase + i];    // 1..51
            float w0 = w0_sh[rowbase + i];
            float w1 = w1_sh[rowbase + i];
            int   s1 = min(s0 + 1, DMAX_ + 1);
            // 128-bit shift left by s (1 <= s <= 51 < 64)
            unsigned long long alo = lo << s0;
            unsigned long long ahi = (hi << s0) | (lo >> (64 - s0));
            unsigned long long blo = lo << s1;
            unsigned long long bhi = (hi << s1) | (lo >> (64 - s1));
            while (alo) { int t = __ffsll(alo) - 1;      alo &= alo - 1; I_sh[t*HB_ + tid] += w0; }
            while (ahi) { int t = 64 + __ffsll(ahi) - 1; ahi &= ahi - 1; I_sh[t*HB_ + tid] += w0; }
            while (blo) { int t = __ffsll(blo) - 1;      blo &= blo - 1; I_sh[t*HB_ + tid] += w1; }
            while (bhi) { int t = 64 + __ffsll(bhi) - 1; bhi &= bhi - 1; I_sh[t*HB_ + tid] += w1; }
        }
    }
    __syncthreads();

    // ---- Phase 3: LIF scan (thread h = hb*128 + tid) ----
    float v = 0.f;       // VRESET
    int   ref = 0;
    float a0 = 0.f, a1 = 0.f, a2 = 0.f, a3 = 0.f;
    #pragma unroll
    for (int t = 0; t < T_; t++) {
        float I  = I_sh[t*HB_ + tid];
        bool  nr = (ref <= 0);
        float vn = nr ? (v + 0.1f * (I - v)) : v;            // DT/TAU = 0.1, VRESET = 0
        float spk = (nr && (vn - 1.0f >= 0.f)) ? 1.f : 0.f;  // spike_fn(v_new - THR) * not_ref
        v   = (spk != 0.f) ? 0.f : vn;
        ref = (spk != 0.f) ? 2 : max(ref - 1, 0);
        a0 += spk * mask_sh[0*T_ + t];
        a1 += spk * mask_sh[1*T_ + t];
        a2 += spk * mask_sh[2*T_ + t];
        a3 += spk * mask_sh[3*T_ + t];
    }

    // ---- Phase 4: readout + deterministic block reduction ----
    float wr = w_read[hb*HB_ + tid];
    float c0 = a0 * wr, c1 = a1 * wr, c2 = a2 * wr, c3 = a3 * wr;
    #pragma unroll
    for (int off = 16; off; off >>= 1) {
        c0 += __shfl_down_sync(0xFFFFFFFFu, c0, off);
        c1 += __shfl_down_sync(0xFFFFFFFFu, c1, off);
        c2 += __shfl_down_sync(0xFFFFFFFFu, c2, off);
        c3 += __shfl_down_sync(0xFFFFFFFFu, c3, off);
    }
    int lane = tid & 31, warp = tid >> 5;
    if (lane == 0) {
        red[warp*4 + 0] = c0;
        red[warp*4 + 1] = c1;
        red[warp*4 + 2] = c2;
        red[warp*4 + 3] = c3;
    }
    __syncthreads();
    if (tid < K_) {
        float s = red[tid] + red[4 + tid] + red[8 + tid] + red[12 + tid];
        g_partials[(b*NHB_ + hb)*K_ + tid] = s;
    }
}

__global__ void snn_reduce_kernel(const float* __restrict__ b_read, float* __restrict__ out)
{
    int tid = threadIdx.x;               // 0..127  -> (b, k)
    int b = tid >> 2, k = tid & 3;
    float s = b_read[0];
    #pragma unroll
    for (int hb = 0; hb < NHB_; hb++)
        s += g_partials[(b*NHB_ + hb)*K_ + k];
    out[b*K_ + k] = s;
}

extern "C" void kernel_launch(void* const* d_in, const int* in_sizes, int n_in,
                              void* d_out, int out_size)
{
    (void)in_sizes; (void)n_in; (void)out_size;
    const float* spikes    = (const float*)d_in[0];   // [32,128,64]
    const float* w_ih      = (const float*)d_in[1];   // [512,64]
    const float* delay_raw = (const float*)d_in[2];   // [512,64]
    const float* w_read    = (const float*)d_in[3];   // [512]
    const float* b_read    = (const float*)d_in[4];   // scalar
    const float* slot_mask = (const float*)d_in[5];   // [4,128]

    const size_t SMEM = (size_t)I_ELEMS*4            // I tile
                      + (size_t)TAP_ELEMS*4*3        // w0, w1, s
                      + (size_t)K_*T_*4              // mask
                      + (size_t)NIN_*8*2             // xlo/xhi
                      + 16*4;                        // red
    cudaFuncSetAttribute(snn_main_kernel,
                         cudaFuncAttributeMaxDynamicSharedMemorySize, (int)SMEM);

    dim3 grid(NHB_, B_);
    snn_main_kernel<<<grid, HB_, SMEM>>>(spikes, w_ih, delay_raw, w_read, slot_mask);
    snn_reduce_kernel<<<1, B_*K_>>>(b_read, (float*)d_out);
}

// round 2
// speedup vs baseline: 1.5118x; 1.5118x over previous
#include <cuda_runtime.h>
#include <cstdint>

#define B_    32
#define T_    128
#define NIN_  64
#define H_    512
#define DMAX_ 50
#define K_    4
#define HB_   128           // h per block
#define NHB_  (H_/HB_)      // 4 h-tiles
#define THREADS 512
#define NBLK  (B_ * NHB_)   // 128

// deterministic partial sums: [b][hb][k]
__device__ float g_partials[B_ * NHB_ * K_];
__device__ unsigned int g_counter = 0;

__global__ __launch_bounds__(THREADS, 1)
void snn_main_kernel(const float* __restrict__ spikes,      // [B,T,NIN]
                     const float* __restrict__ w_ih,        // [H,NIN]
                     const float* __restrict__ delay_raw,   // [H,NIN]
                     const float* __restrict__ w_read,      // [H]
                     const float* __restrict__ b_read,      // scalar
                     const float* __restrict__ slot_mask,   // [K,T]
                     float* __restrict__ out)               // [B,K]
{
    extern __shared__ char smem_raw[];
    float*  I_sh    = (float*)smem_raw;                    // [T][HB]   65536 B
    float2* wp_sh   = (float2*)(I_sh + T_*HB_);            // [NIN][HB] 65536 B
    unsigned char* s_sh = (unsigned char*)(wp_sh + NIN_*HB_); // [NIN][HB] 8192 B
    unsigned int* maskA = (unsigned int*)(s_sh + NIN_*HB_);   // [T][2]  1024 B
    float*  mask_sh = (float*)(maskA + T_*2);              // [K][T]    2048 B
    float*  red     = mask_sh + K_*T_;                     // 16 floats

    __shared__ int is_last;

    const int tid = threadIdx.x;
    const int hb  = blockIdx.x;
    const int b   = blockIdx.y;

    // ---- zero I tile ----
    #pragma unroll
    for (int r = 0; r < (T_*HB_)/THREADS; r++)
        I_sh[r*THREADS + tid] = 0.f;

    // slot mask -> smem
    #pragma unroll
    for (int j = tid; j < K_*T_; j += THREADS) mask_sh[j] = slot_mask[j];

    // ---- Phase A: per-timestep 64-bit active-input masks (deterministic ballots) ----
    {
        const float* xb = spikes + (size_t)b * T_ * NIN_;
        #pragma unroll
        for (int rep = 0; rep < (T_*NIN_)/THREADS; rep++) {
            int idx = rep*THREADS + tid;           // t = idx>>6, i = idx&63
            float v = xb[idx];
            unsigned int ball = __ballot_sync(0xFFFFFFFFu, v != 0.f);
            if ((tid & 31) == 0) {
                int t = idx >> 6;
                int half = (idx >> 5) & 1;
                maskA[t*2 + half] = ball;
            }
        }
    }

    // ---- Phase 1c: tap params, transposed [i][h] layout ----
    {
        const int gbase = hb * HB_ * NIN_;
        #pragma unroll
        for (int rep = 0; rep < (HB_*NIN_)/THREADS; rep++) {
            int idx = rep*THREADS + tid;
            int hh = idx >> 6;
            int ii = idx & 63;
            float raw  = delay_raw[gbase + idx];
            float w    = w_ih[gbase + idx];
            float d    = (float)DMAX_ / (1.f + expf(-raw));  // sigmoid * DMAX
            float d0   = floorf(d);
            float frac = d - d0;
            int   s0   = (int)d0 + 1;                        // read-before-insert => +1
            wp_sh[ii*HB_ + hh] = make_float2(w*(1.f-frac), w*frac);
            s_sh [ii*HB_ + hh] = (unsigned char)s0;
        }
    }
    __syncthreads();

    // ---- Phase B: set-bit driven scatter; lanes = h, uniform bit scan ----
    if (tid < HB_) {
        const int h = tid;
        #pragma unroll 1
        for (int t = 0; t < T_ - 1; t++) {
            unsigned int m0 = maskA[t*2 + 0];
            unsigned int m1 = maskA[t*2 + 1];
            while (m0) {
                int i = __ffs(m0) - 1; m0 &= m0 - 1;
                float2 w = wp_sh[i*HB_ + h];
                int s0 = (int)s_sh[i*HB_ + h];
                int t0 = t + s0;
                int t1 = t + min(s0 + 1, DMAX_ + 1);
                if (t0 < T_) I_sh[t0*HB_ + h] += w.x;
                if (t1 < T_) I_sh[t1*HB_ + h] += w.y;
            }
            while (m1) {
                int i = 32 + __ffs(m1) - 1; m1 &= m1 - 1;
                float2 w = wp_sh[i*HB_ + h];
                int s0 = (int)s_sh[i*HB_ + h];
                int t0 = t + s0;
                int t1 = t + min(s0 + 1, DMAX_ + 1);
                if (t0 < T_) I_sh[t0*HB_ + h] += w.x;
                if (t1 < T_) I_sh[t1*HB_ + h] += w.y;
            }
        }
    }
    __syncthreads();

    // ---- Phase 3: LIF scan + masked accumulation (threads 0..127 = h) ----
    if (tid < HB_) {
        float v = 0.f;       // VRESET
        int   ref = 0;
        float a0 = 0.f, a1 = 0.f, a2 = 0.f, a3 = 0.f;
        #pragma unroll
        for (int t = 0; t < T_; t++) {
            float I  = I_sh[t*HB_ + tid];
            bool  nr = (ref <= 0);
            float vn = nr ? (v + 0.1f * (I - v)) : v;            // DT/TAU=0.1, VRESET=0
            float spk = (nr && (vn - 1.0f >= 0.f)) ? 1.f : 0.f;  // spike_fn(v-THR)*not_ref
            v   = (spk != 0.f) ? 0.f : vn;
            ref = (spk != 0.f) ? 2 : max(ref - 1, 0);
            a0 += spk * mask_sh[0*T_ + t];
            a1 += spk * mask_sh[1*T_ + t];
            a2 += spk * mask_sh[2*T_ + t];
            a3 += spk * mask_sh[3*T_ + t];
        }

        float wr = w_read[hb*HB_ + tid];
        float c0 = a0 * wr, c1 = a1 * wr, c2 = a2 * wr, c3 = a3 * wr;
        #pragma unroll
        for (int off = 16; off; off >>= 1) {
            c0 += __shfl_down_sync(0xFFFFFFFFu, c0, off);
            c1 += __shfl_down_sync(0xFFFFFFFFu, c1, off);
            c2 += __shfl_down_sync(0xFFFFFFFFu, c2, off);
            c3 += __shfl_down_sync(0xFFFFFFFFu, c3, off);
        }
        int lane = tid & 31, warp = tid >> 5;
        if (lane == 0) {
            red[warp*4 + 0] = c0;
            red[warp*4 + 1] = c1;
            red[warp*4 + 2] = c2;
            red[warp*4 + 3] = c3;
        }
    }
    __syncthreads();
    if (tid < K_) {
        float s = red[tid] + red[4 + tid] + red[8 + tid] + red[12 + tid];
        g_partials[(b*NHB_ + hb)*K_ + tid] = s;
    }
    __syncthreads();

    // ---- fused deterministic final reduction: last block writes output ----
    if (tid == 0) {
        __threadfence();
        unsigned int done = atomicAdd(&g_counter, 1u);
        is_last = (done == NBLK - 1) ? 1 : 0;
    }
    __syncthreads();
    if (is_last) {
        if (tid == 0) g_counter = 0;   // reset for next graph replay
        __threadfence();
        if (tid < B_ * K_) {
            int bb = tid >> 2, kk = tid & 3;
            float s = b_read[0];
            #pragma unroll
            for (int h2 = 0; h2 < NHB_; h2++)
                s += __ldcg(&g_partials[(bb*NHB_ + h2)*K_ + kk]);
            out[bb*K_ + kk] = s;
        }
    }
}

extern "C" void kernel_launch(void* const* d_in, const int* in_sizes, int n_in,
                              void* d_out, int out_size)
{
    (void)in_sizes; (void)n_in; (void)out_size;
    const float* spikes    = (const float*)d_in[0];   // [32,128,64]
    const float* w_ih      = (const float*)d_in[1];   // [512,64]
    const float* delay_raw = (const float*)d_in[2];   // [512,64]
    const float* w_read    = (const float*)d_in[3];   // [512]
    const float* b_read    = (const float*)d_in[4];   // scalar
    const float* slot_mask = (const float*)d_in[5];   // [4,128]

    const size_t SMEM = (size_t)T_*HB_*4              // I tile        65536
                      + (size_t)NIN_*HB_*8            // wp (float2)   65536
                      + (size_t)NIN_*HB_              // s (u8)         8192
                      + (size_t)T_*2*4                // maskA          1024
                      + (size_t)K_*T_*4               // slot mask      2048
                      + 16*4;                         // red
    cudaFuncSetAttribute(snn_main_kernel,
                         cudaFuncAttributeMaxDynamicSharedMemorySize, (int)SMEM);

    dim3 grid(NHB_, B_);
    snn_main_kernel<<<grid, THREADS, SMEM>>>(spikes, w_ih, delay_raw, w_read,
                                             b_read, slot_mask, (float*)d_out);
}

// round 3
// speedup vs baseline: 2.2855x; 1.5118x over previous
#include <cuda_runtime.h>
#include <cstdint>

#define B_    32
#define T_    128
#define NIN_  64
#define H_    512
#define DMAX_ 50
#define K_    4
#define HB_   128           // h per block
#define NHB_  (H_/NHB_HELPER)
#define NHB_HELPER HB_
#undef NHB_
#define NHB_  (H_/HB_)      // 4 h-tiles
#define THREADS 512
#define NBLK  (B_ * NHB_)   // 128

#define TPAD  130                 // 128 real rows + 2 clamp/dump rows
#define ICOPY (TPAD * HB_)        // floats per I copy (16640)

// deterministic partial sums: [b][hb][k]
__device__ float g_partials[B_ * NHB_ * K_];
__device__ unsigned int g_counter = 0;

__global__ __launch_bounds__(THREADS, 1)
void snn_main_kernel(const float* __restrict__ spikes,      // [B,T,NIN]
                     const float* __restrict__ w_ih,        // [H,NIN]
                     const float* __restrict__ delay_raw,   // [H,NIN]
                     const float* __restrict__ w_read,      // [H]
                     const float* __restrict__ b_read,      // scalar
                     const float* __restrict__ slot_mask,   // [K,T]
                     float* __restrict__ out)               // [B,K]
{
    extern __shared__ char smem_raw[];
    float*  I_sh    = (float*)smem_raw;                       // 2 copies: [TPAD][HB] each, 133120 B
    float2* wp_sh   = (float2*)(I_sh + 2*ICOPY);              // [NIN][HB] 65536 B
    unsigned char* s_sh = (unsigned char*)(wp_sh + NIN_*HB_); // [NIN][HB]  8192 B
    unsigned int* maskA = (unsigned int*)(s_sh + NIN_*HB_);   // [T][2]     1024 B
    float*  mask_sh = (float*)(maskA + T_*2);                 // [K][T]     2048 B
    float*  red     = mask_sh + K_*T_;                        // 16 floats

    __shared__ int is_last;

    const int tid = threadIdx.x;
    const int hb  = blockIdx.x;
    const int b   = blockIdx.y;

    // ---- zero both I copies (incl. dump rows) ----
    #pragma unroll
    for (int r = tid; r < 2*ICOPY; r += THREADS)
        I_sh[r] = 0.f;

    // slot mask -> smem
    #pragma unroll
    for (int j = tid; j < K_*T_; j += THREADS) mask_sh[j] = slot_mask[j];

    // ---- Phase A: per-timestep 64-bit active-input masks (deterministic ballots) ----
    {
        const float* xb = spikes + (size_t)b * T_ * NIN_;
        #pragma unroll
        for (int rep = 0; rep < (T_*NIN_)/THREADS; rep++) {
            int idx = rep*THREADS + tid;           // t = idx>>6, i = idx&63
            float v = xb[idx];
            unsigned int ball = __ballot_sync(0xFFFFFFFFu, v != 0.f);
            if ((tid & 31) == 0) {
                int t = idx >> 6;
                int half = (idx >> 5) & 1;
                maskA[t*2 + half] = ball;
            }
        }
    }

    // ---- Phase 1c: tap params, transposed [i][h] layout ----
    {
        const int gbase = hb * HB_ * NIN_;
        #pragma unroll
        for (int rep = 0; rep < (HB_*NIN_)/THREADS; rep++) {
            int idx = rep*THREADS + tid;
            int hh = idx >> 6;
            int ii = idx & 63;
            float raw  = delay_raw[gbase + idx];
            float w    = w_ih[gbase + idx];
            float d    = (float)DMAX_ / (1.f + expf(-raw));  // sigmoid * DMAX
            float d0   = floorf(d);
            float frac = d - d0;
            int   s0   = (int)d0 + 1;                        // read-before-insert => +1
            wp_sh[ii*HB_ + hh] = make_float2(w*(1.f-frac), w*frac);
            s_sh [ii*HB_ + hh] = (unsigned char)s0;
        }
    }
    __syncthreads();

    // ---- Phase B: event-driven scatter, 2 warp-groups by input half, privatized I ----
    // Branch-free event body: t0 clamped into dump rows, taps always go to (t0, t0+1)
    // (constant +128 float offset -> ptxas proves no alias -> parallel LDS/STS pair).
    if (tid < 2*HB_) {
        const int grp = tid >> 7;                 // 0: i<32 events, 1: i>=32
        const int h   = tid & (HB_-1);
        float* __restrict__ Ic = I_sh + grp * ICOPY;
        const int ibase = grp << 5;
        #pragma unroll 1
        for (int t = 0; t < T_ - 1; t++) {
            unsigned int m = maskA[t*2 + grp];
            while (m) {
                int j = __ffs(m) - 1; m &= m - 1;
                int i = ibase + j;
                float2 w = wp_sh[i*HB_ + h];
                int s0 = (int)s_sh[i*HB_ + h];
                bool cap = (s0 > DMAX_);                  // s0 == 51 -> both taps same slot
                float wx = cap ? (w.x + w.y) : w.x;
                float wy = cap ? 0.f : w.y;
                int t0 = min(t + s0, T_);                 // <= 128 (dump row)
                int o0 = t0*HB_ + h;
                float a0 = Ic[o0];
                float a1 = Ic[o0 + HB_];                  // t0+1 <= 129 (dump row)
                Ic[o0]       = a0 + wx;
                Ic[o0 + HB_] = a1 + wy;
            }
        }
    }
    __syncthreads();

    // ---- Phase 3: LIF scan + masked accumulation (threads 0..127 = h) ----
    if (tid < HB_) {
        float v = 0.f;       // VRESET
        int   ref = 0;
        float a0 = 0.f, a1 = 0.f, a2 = 0.f, a3 = 0.f;
        #pragma unroll
        for (int t = 0; t < T_; t++) {
            float I  = I_sh[t*HB_ + tid] + I_sh[ICOPY + t*HB_ + tid];
            bool  nr = (ref <= 0);
            float vn = nr ? (v + 0.1f * (I - v)) : v;            // DT/TAU=0.1, VRESET=0
            float spk = (nr && (vn - 1.0f >= 0.f)) ? 1.f : 0.f;  // spike_fn(v-THR)*not_ref
            v   = (spk != 0.f) ? 0.f : vn;
            ref = (spk != 0.f) ? 2 : max(ref - 1, 0);
            a0 += spk * mask_sh[0*T_ + t];
            a1 += spk * mask_sh[1*T_ + t];
            a2 += spk * mask_sh[2*T_ + t];
            a3 += spk * mask_sh[3*T_ + t];
        }

        float wr = w_read[hb*HB_ + tid];
        float c0 = a0 * wr, c1 = a1 * wr, c2 = a2 * wr, c3 = a3 * wr;
        #pragma unroll
        for (int off = 16; off; off >>= 1) {
            c0 += __shfl_down_sync(0xFFFFFFFFu, c0, off);
            c1 += __shfl_down_sync(0xFFFFFFFFu, c1, off);
            c2 += __shfl_down_sync(0xFFFFFFFFu, c2, off);
            c3 += __shfl_down_sync(0xFFFFFFFFu, c3, off);
        }
        int lane = tid & 31, warp = tid >> 5;
        if (lane == 0) {
            red[warp*4 + 0] = c0;
            red[warp*4 + 1] = c1;
            red[warp*4 + 2] = c2;
            red[warp*4 + 3] = c3;
        }
    }
    __syncthreads();
    if (tid < K_) {
        float s = red[tid] + red[4 + tid] + red[8 + tid] + red[12 + tid];
        g_partials[(b*NHB_ + hb)*K_ + tid] = s;
    }
    __syncthreads();

    // ---- fused deterministic final reduction: last block writes output ----
    if (tid == 0) {
        __threadfence();
        unsigned int done = atomicAdd(&g_counter, 1u);
        is_last = (done == NBLK - 1) ? 1 : 0;
    }
    __syncthreads();
    if (is_last) {
        if (tid == 0) g_counter = 0;   // reset for next graph replay
        __threadfence();
        if (tid < B_ * K_) {
            int bb = tid >> 2, kk = tid & 3;
            float s = b_read[0];
            #pragma unroll
            for (int h2 = 0; h2 < NHB_; h2++)
                s += __ldcg(&g_partials[(bb*NHB_ + h2)*K_ + kk]);
            out[bb*K_ + kk] = s;
        }
    }
}

extern "C" void kernel_launch(void* const* d_in, const int* in_sizes, int n_in,
                              void* d_out, int out_size)
{
    (void)in_sizes; (void)n_in; (void)out_size;
    const float* spikes    = (const float*)d_in[0];   // [32,128,64]
    const float* w_ih      = (const float*)d_in[1];   // [512,64]
    const float* delay_raw = (const float*)d_in[2];   // [512,64]
    const float* w_read    = (const float*)d_in[3];   // [512]
    const float* b_read    = (const float*)d_in[4];   // scalar
    const float* slot_mask = (const float*)d_in[5];   // [4,128]

    const size_t SMEM = (size_t)2*ICOPY*4             // 2 I copies   133120
                      + (size_t)NIN_*HB_*8            // wp (float2)   65536
                      + (size_t)NIN_*HB_              // s (u8)         8192
                      + (size_t)T_*2*4                // maskA          1024
                      + (size_t)K_*T_*4               // slot mask      2048
                      + 16*4;                         // red
    cudaFuncSetAttribute(snn_main_kernel,
                         cudaFuncAttributeMaxDynamicSharedMemorySize, (int)SMEM);

    dim3 grid(NHB_, B_);
    snn_main_kernel<<<grid, THREADS, SMEM>>>(spikes, w_ih, delay_raw, w_read,
                                             b_read, slot_mask, (float*)d_out);
}